// round 9
// baseline (speedup 1.0000x reference)
#include <cuda_runtime.h>
#include <cuda_fp16.h>
#include <stdint.h>
#include <math.h>

#define Nn    4096
#define INF   512
#define OUTF  128
#define CN    16384
#define TOTD  67108864.0
#define SCALE 2.5f
#define KC    64
#define NCHUNK 64

// gemm2m SMEM layout (bytes, dynamic)
#define ATT_OFF 0u          // 3 x 32768 fp32 att stages
#define MK_OFF  98304u      // 3 x 8192  u8 mask stages
#define AF_OFF  122880u     // 2 x 16384 f16 A tiles
#define BF_OFF  155648u     // 3 x 16384 f16 B tiles
#define SMEM2   204800

__device__ __forceinline__ uint32_t smem_to_u32(const void* p) {
    uint32_t a;
    asm("{ .reg .u64 t; cvta.to.shared.u64 t, %1; cvt.u32.u64 %0, t; }" : "=r"(a) : "l"(p));
    return a;
}
__device__ __forceinline__ uint32_t packh2(float lo, float hi) {
    uint32_t r;
    asm("cvt.rn.f16x2.f32 %0, %1, %2;" : "=r"(r) : "f"(hi), "f"(lo));
    return r;
}
#define LDSM4(r, a)                                                                   \
    asm volatile("ldmatrix.sync.aligned.m8n8.x4.shared.b16 {%0,%1,%2,%3}, [%4];"      \
        : "=r"((r)[0]), "=r"((r)[1]), "=r"((r)[2]), "=r"((r)[3]) : "r"(a))
#define MMAH(d, a, b0, b1)                                                            \
    asm volatile("mma.sync.aligned.m16n8k16.row.col.f32.f16.f16.f32 "                 \
        "{%0,%1,%2,%3},{%4,%5,%6,%7},{%8,%9},{%0,%1,%2,%3};"                          \
        : "+f"((d)[0]), "+f"((d)[1]), "+f"((d)[2]), "+f"((d)[3])                      \
        : "r"((a)[0]), "r"((a)[1]), "r"((a)[2]), "r"((a)[3]), "r"(b0), "r"(b1))
#define CPASYNC16(dst, src)                                                           \
    asm volatile("cp.async.cg.shared.global [%0], [%1], 16;" :: "r"(dst), "l"(src))
#define CPCOMMIT() asm volatile("cp.async.commit_group;" ::: "memory")
#define CPWAIT1()  asm volatile("cp.async.wait_group 1;" ::: "memory")
#define CPWAITALL() asm volatile("cp.async.wait_group 0;" ::: "memory")

__device__ __forceinline__ uint32_t swz(uint32_t off) { return off ^ ((off >> 3) & 0x70); }

// ---------------- scratch ----------------
__device__ float  g_h[Nn * OUTF];
__device__ float  g_Wt[INF * OUTF];
__device__ double g_part[1024];
__device__ float  g_mean;
__device__ float  g_colpart[64 * Nn];
__device__ float  g_rs[Nn];              // 1024 * 2.5 / S[j]
__device__ int    g_mstride;
__device__ unsigned short g_Bf[OUTF * Nn];   // [f][k] fp16 of g[k][f]*1024

// ---------------- mask dtype detection ----------------
__global__ void k_detect(const unsigned char* mask) {
    __shared__ int s[256];
    int nz = 0;
    for (int i = threadIdx.x; i < 65536; i += 256)
        if ((i & 3) != 0 && mask[i]) nz++;
    s[threadIdx.x] = nz;
    __syncthreads();
    for (int o = 128; o > 0; o >>= 1) {
        if (threadIdx.x < o) s[threadIdx.x] += s[threadIdx.x + o];
        __syncthreads();
    }
    if (threadIdx.x == 0) g_mstride = (s[0] == 0) ? 4 : 1;
}

// ---------------- W transpose ----------------
__global__ void k_wt(const float* __restrict__ W) {
    int o = blockIdx.x * 256 + threadIdx.x;
    int f = o & (OUTF - 1);
    int k = o >> 7;
    g_Wt[o] = W[f * INF + k];
}

// ---------------- mean ----------------
__global__ void k_meanpart(const float4* __restrict__ att4) {
    float acc = 0.f;
    int stride = gridDim.x * blockDim.x;
    int n4 = (CN * Nn) / 4;
#pragma unroll 4
    for (int i = blockIdx.x * blockDim.x + threadIdx.x; i < n4; i += stride) {
        float4 v = att4[i];
        acc += (v.x + v.y) + (v.z + v.w);
    }
    __shared__ double s[256];
    s[threadIdx.x] = (double)acc;
    __syncthreads();
    for (int o = 128; o > 0; o >>= 1) {
        if (threadIdx.x < o) s[threadIdx.x] += s[threadIdx.x + o];
        __syncthreads();
    }
    if (threadIdx.x == 0) g_part[blockIdx.x] = s[0];
}

__global__ void k_meanfin() {
    __shared__ double s[256];
    int t = threadIdx.x;
    double a = g_part[t] + g_part[t + 256] + g_part[t + 512] + g_part[t + 768];
    s[t] = a;
    __syncthreads();
    for (int o = 128; o > 0; o >>= 1) {
        if (t < o) s[t] += s[t + o];
        __syncthreads();
    }
    if (t == 0) g_mean = (float)(s[0] / TOTD);
}

// ---------------- column sums (float4 per thread) ----------------
__global__ void k_colsum(const float4* __restrict__ att4) {
    float mean = g_mean;
    int col4 = blockIdx.x * 256 + threadIdx.x;    // 0..1023
    int r0 = blockIdx.y * 256;
    const float4* p = att4 + (size_t)r0 * 1024 + col4;
    float ax = 0.f, ay = 0.f, az = 0.f, aw = 0.f;
#pragma unroll 8
    for (int i = 0; i < 256; i++) {
        float4 v = p[(size_t)i * 1024];
        ax += (v.x > mean) ? __expf(v.x) : 0.f;
        ay += (v.y > mean) ? __expf(v.y) : 0.f;
        az += (v.z > mean) ? __expf(v.z) : 0.f;
        aw += (v.w > mean) ? __expf(v.w) : 0.f;
    }
    float* cp = g_colpart + (size_t)blockIdx.y * Nn + col4 * 4;
    *(float4*)cp = make_float4(ax, ay, az, aw);
}

__global__ void k_rs() {
    int j = blockIdx.x * 256 + threadIdx.x;
    float s = 0.f;
#pragma unroll 8
    for (int ch = 0; ch < 64; ch++) s += g_colpart[ch * Nn + j];
    g_rs[j] = 1024.f * SCALE / s;
}

// ---------------- GEMM1: h = x @ Wt ----------------
__global__ __launch_bounds__(256) void k_gemm1(const float* __restrict__ x) {
    __shared__ __align__(16) float As[16][32];
    __shared__ __align__(16) float Bs[16][128];
    int tid = threadIdx.x;
    int r0 = blockIdx.x * 32;
    int tr = tid >> 4;
    int tc = tid & 15;
    float acc[2][8];
#pragma unroll
    for (int i = 0; i < 2; i++)
#pragma unroll
        for (int j = 0; j < 8; j++) acc[i][j] = 0.f;

    for (int k0 = 0; k0 < INF; k0 += 16) {
        if (tid < 128) {
            int row = tid >> 2, c4 = tid & 3;
            float4 v = *(const float4*)(x + (size_t)(r0 + row) * INF + k0 + c4 * 4);
            As[c4 * 4 + 0][row] = v.x;
            As[c4 * 4 + 1][row] = v.y;
            As[c4 * 4 + 2][row] = v.z;
            As[c4 * 4 + 3][row] = v.w;
        }
#pragma unroll
        for (int q = 0; q < 2; q++) {
            int g = tid + q * 256;
            int kk = g >> 5, f4 = g & 31;
            *(float4*)&Bs[kk][f4 * 4] = *(const float4*)(g_Wt + (k0 + kk) * OUTF + f4 * 4);
        }
        __syncthreads();
#pragma unroll
        for (int kk = 0; kk < 16; kk++) {
            float a0 = As[kk][tr * 2], a1 = As[kk][tr * 2 + 1];
            float b[8];
            *(float4*)(b)     = *(const float4*)&Bs[kk][tc * 8];
            *(float4*)(b + 4) = *(const float4*)&Bs[kk][tc * 8 + 4];
#pragma unroll
            for (int j = 0; j < 8; j++) {
                acc[0][j] += a0 * b[j];
                acc[1][j] += a1 * b[j];
            }
        }
        __syncthreads();
    }
#pragma unroll
    for (int i = 0; i < 2; i++) {
        float* op = g_h + (size_t)(r0 + tr * 2 + i) * OUTF + tc * 8;
        *(float4*)op       = make_float4(acc[i][0], acc[i][1], acc[i][2], acc[i][3]);
        *(float4*)(op + 4) = make_float4(acc[i][4], acc[i][5], acc[i][6], acc[i][7]);
    }
}

// ---------------- B prep ----------------
__global__ void k_bprep() {
    __shared__ float tile[32][33];
    __shared__ float rss[32];
    int k0 = blockIdx.x * 32, f0 = blockIdx.y * 32;
    int t = threadIdx.x;
    {
        int ki = t >> 3, f4 = (t & 7) * 4;
        float4 v = *(const float4*)(g_h + (size_t)(k0 + ki) * OUTF + f0 + f4);
        tile[ki][f4 + 0] = v.x; tile[ki][f4 + 1] = v.y;
        tile[ki][f4 + 2] = v.z; tile[ki][f4 + 3] = v.w;
    }
    if (t < 32) rss[t] = g_rs[k0 + t];
    __syncthreads();
    int fi = t >> 3, k4 = (t & 7) * 4;
    uint32_t p01 = packh2(tile[k4 + 0][fi] * rss[k4 + 0], tile[k4 + 1][fi] * rss[k4 + 1]);
    uint32_t p23 = packh2(tile[k4 + 2][fi] * rss[k4 + 2], tile[k4 + 3][fi] * rss[k4 + 3]);
    size_t o = (size_t)(f0 + fi) * Nn + k0 + k4;
    *(uint2*)(g_Bf + o) = make_uint2(p01, p23);
}

// ---------------- GEMM2: fp16 mma.sync, fully async cp.async pipeline ----------------
__global__ __launch_bounds__(256, 1) void k_gemm2m(const float* __restrict__ att,
                                                   const unsigned char* __restrict__ mask,
                                                   float* __restrict__ out) {
    extern __shared__ __align__(128) char sm[];
    uint32_t smb = smem_to_u32(sm);
    const int tid = threadIdx.x, lane = tid & 31, w = tid >> 5;
    const int r0 = blockIdx.x * 128;
    const float mean = g_mean;
    const int mstride = g_mstride;
    const int wm0 = (w & 3) * 32;
    const int wn0 = (w >> 2) * 64;

    float acc[2][8][4];
#pragma unroll
    for (int mt = 0; mt < 2; mt++)
#pragma unroll
        for (int nt = 0; nt < 8; nt++)
#pragma unroll
            for (int q = 0; q < 4; q++) acc[mt][nt][q] = 0.f;

    const int li = lane >> 3;
    const uint32_t aRow = wm0 + (li & 1) * 8 + (lane & 7);
    const uint32_t aKof = (li >> 1) * 16;
    const uint32_t bRow = wn0 + ((lane >> 4) & 1) * 8 + (lane & 7);
    const uint32_t bKof = ((lane >> 3) & 1) * 16;

    // issue one full stage of cp.async for chunk c_ into stage slot st_
#define CPSTAGE(c_, st_)                                                              \
    {                                                                                 \
        int kc = (c_) * KC;                                                           \
        _Pragma("unroll")                                                             \
        for (int j = 0; j < 8; j++) {                                                 \
            int idx = j * 256 + tid;                                                  \
            int row = idx >> 4, c16 = idx & 15;                                       \
            CPASYNC16(smb + ATT_OFF + (st_) * 32768u + (uint32_t)idx * 16u,           \
                      att + (size_t)(r0 + row) * Nn + kc + c16 * 4);                  \
        }                                                                             \
        if (mstride == 1) {                                                           \
            _Pragma("unroll")                                                         \
            for (int j = 0; j < 2; j++) {                                             \
                int idx = j * 256 + tid;                                              \
                int row = idx >> 2, c16 = idx & 3;                                    \
                CPASYNC16(smb + MK_OFF + (st_) * 8192u + (uint32_t)idx * 16u,         \
                          mask + (size_t)(r0 + row) * Nn + kc + c16 * 16);            \
            }                                                                         \
        }                                                                             \
        _Pragma("unroll")                                                             \
        for (int j = 0; j < 4; j++) {                                                 \
            int g = j * 256 + tid;                                                    \
            int f = g >> 3, seg = g & 7;                                              \
            CPASYNC16(smb + BF_OFF + (st_) * 16384u + swz((uint32_t)(f * 128 + seg * 16)), \
                      g_Bf + (size_t)f * Nn + kc + seg * 8);                          \
        }                                                                             \
        CPCOMMIT();                                                                   \
    }

#define CONVERT(c_, st_, ca_)                                                         \
    {                                                                                 \
        _Pragma("unroll")                                                             \
        for (int i = 0; i < 8; i++) {                                                 \
            int idx = i * 256 + tid;                                                  \
            int m = idx >> 4, c4 = idx & 15;                                          \
            float4 v = *(const float4*)(sm + ATT_OFF + (st_) * 32768u + (uint32_t)idx * 16u); \
            uint32_t mk;                                                              \
            if (mstride == 1) {                                                       \
                mk = *(const uint32_t*)(sm + MK_OFF + (st_) * 8192u + (uint32_t)(m * 64 + c4 * 4)); \
            } else {                                                                  \
                int4 mi = *(const int4*)((const int*)mask + (size_t)(r0 + m) * Nn + (c_) * KC + c4 * 4); \
                mk = (mi.x ? 1u : 0u) | (mi.y ? 0x100u : 0u) |                        \
                     (mi.z ? 0x10000u : 0u) | (mi.w ? 0x1000000u : 0u);               \
            }                                                                         \
            float a0 = ((mk & 0xFFu) && v.x > mean) ? __expf(v.x) : 0.f;              \
            float a1 = ((mk & 0xFF00u) && v.y > mean) ? __expf(v.y) : 0.f;            \
            float a2 = ((mk & 0xFF0000u) && v.z > mean) ? __expf(v.z) : 0.f;          \
            float a3 = ((mk & 0xFF000000u) && v.w > mean) ? __expf(v.w) : 0.f;        \
            uint32_t p01 = packh2(a0, a1);                                            \
            uint32_t p23 = packh2(a2, a3);                                            \
            *(uint2*)(sm + AF_OFF + (ca_) * 16384u + swz((uint32_t)(m * 128 + c4 * 8))) = \
                make_uint2(p01, p23);                                                 \
        }                                                                             \
    }

    // prologue: stages 0 and 1 in flight
    CPSTAGE(0, 0);
    CPSTAGE(1, 1);

    int st = 0;
    for (int c = 0; c < NCHUNK; c++) {
        if (c < NCHUNK - 2) { CPWAIT1(); } else { CPWAITALL(); }
        __syncthreads();

        CONVERT(c, st, (c & 1));
        __syncthreads();

        if (c + 2 < NCHUNK) {
            int st2 = st + 2; if (st2 >= 3) st2 -= 3;
            CPSTAGE(c + 2, st2);
        }

        // MMA on AF[c&1], BF[st]
        uint32_t abase = smb + AF_OFF + (uint32_t)(c & 1) * 16384u;
        uint32_t bbase = smb + BF_OFF + (uint32_t)st * 16384u;
#pragma unroll
        for (int ks = 0; ks < 4; ks++) {
            uint32_t ah[2][4];
#pragma unroll
            for (int mt = 0; mt < 2; mt++) {
                uint32_t sw = swz((aRow + mt * 16) * 128 + ks * 32 + aKof);
                LDSM4(ah[mt], abase + sw);
            }
#pragma unroll
            for (int nt2 = 0; nt2 < 4; nt2++) {
                uint32_t sw = swz((bRow + nt2 * 16) * 128 + ks * 32 + bKof);
                uint32_t bh[4];
                LDSM4(bh, bbase + sw);
#pragma unroll
                for (int mt = 0; mt < 2; mt++) {
                    MMAH(acc[mt][nt2 * 2],     ah[mt], bh[0], bh[1]);
                    MMAH(acc[mt][nt2 * 2 + 1], ah[mt], bh[2], bh[3]);
                }
            }
        }
        st = (st + 1 == 3) ? 0 : st + 1;
    }

    // epilogue: unscale + permuted store
    const float dsc = 1.f / 1024.f;
    const int orow = lane >> 2, ocol = (lane & 3) * 2;
#pragma unroll
    for (int mt = 0; mt < 2; mt++) {
#pragma unroll
        for (int nt = 0; nt < 8; nt++) {
            int f = wn0 + nt * 8 + ocol;
            int r1 = r0 + wm0 + mt * 16 + orow;
            int n1 = r1 & (Nn - 1), c1 = r1 >> 12;
            *(float2*)(out + (size_t)n1 * 512 + c1 * OUTF + f) =
                make_float2(acc[mt][nt][0] * dsc, acc[mt][nt][1] * dsc);
            int r2 = r1 + 8;
            int n2 = r2 & (Nn - 1), c2 = r2 >> 12;
            *(float2*)(out + (size_t)n2 * 512 + c2 * OUTF + f) =
                make_float2(acc[mt][nt][2] * dsc, acc[mt][nt][3] * dsc);
        }
    }
#undef CPSTAGE
#undef CONVERT
}

// ---------------- launch ----------------
extern "C" void kernel_launch(void* const* d_in, const int* in_sizes, int n_in,
                              void* d_out, int out_size) {
    const float* x = (const float*)d_in[0];
    const float* att = (const float*)d_in[1];
    const float* W = (const float*)d_in[2];
    const unsigned char* mask = (const unsigned char*)d_in[3];
    float* out = (float*)d_out;

    cudaFuncSetAttribute(k_gemm2m, cudaFuncAttributeMaxDynamicSharedMemorySize, SMEM2);

    k_detect<<<1, 256>>>(mask);
    k_wt<<<256, 256>>>(W);
    k_gemm1<<<128, 256>>>(x);
    k_meanpart<<<1024, 256>>>((const float4*)att);
    k_meanfin<<<1, 256>>>();
    k_colsum<<<dim3(4, 64), 256>>>((const float4*)att);
    k_rs<<<16, 256>>>();
    k_bprep<<<dim3(128, 4), 256>>>();
    k_gemm2m<<<128, 256, SMEM2>>>(att, mask, out);
}

// round 10
// speedup vs baseline: 1.2935x; 1.2935x over previous
#include <cuda_runtime.h>
#include <cuda_fp16.h>
#include <stdint.h>
#include <math.h>

#define Nn    4096
#define INF   512
#define OUTF  128
#define CN    16384
#define TOTD  67108864.0
#define SCALE 2.5f
#define KC    64
#define NCHUNK 64

__device__ __forceinline__ uint32_t smem_to_u32(const void* p) {
    uint32_t a;
    asm("{ .reg .u64 t; cvta.to.shared.u64 t, %1; cvt.u32.u64 %0, t; }" : "=r"(a) : "l"(p));
    return a;
}
__device__ __forceinline__ uint32_t packh2(float lo, float hi) {
    uint32_t r;
    asm("cvt.rn.f16x2.f32 %0, %1, %2;" : "=r"(r) : "f"(hi), "f"(lo));
    return r;
}
#define LDSM4(r, a)                                                                   \
    asm volatile("ldmatrix.sync.aligned.m8n8.x4.shared.b16 {%0,%1,%2,%3}, [%4];"      \
        : "=r"((r)[0]), "=r"((r)[1]), "=r"((r)[2]), "=r"((r)[3]) : "r"(a))
#define MMAH(d, a, b0, b1)                                                            \
    asm volatile("mma.sync.aligned.m16n8k16.row.col.f32.f16.f16.f32 "                 \
        "{%0,%1,%2,%3},{%4,%5,%6,%7},{%8,%9},{%0,%1,%2,%3};"                          \
        : "+f"((d)[0]), "+f"((d)[1]), "+f"((d)[2]), "+f"((d)[3])                      \
        : "r"((a)[0]), "r"((a)[1]), "r"((a)[2]), "r"((a)[3]), "r"(b0), "r"(b1))
#define CPASYNC16(dst, src)                                                           \
    asm volatile("cp.async.cg.shared.global [%0], [%1], 16;" :: "r"(dst), "l"(src))
#define CPCOMMIT() asm volatile("cp.async.commit_group;" ::: "memory")
#define CPWAIT0()  asm volatile("cp.async.wait_group 0;" ::: "memory")

__device__ __forceinline__ uint32_t swz(uint32_t off) { return off ^ ((off >> 3) & 0x70); }

// ---------------- scratch ----------------
__device__ float  g_h[Nn * OUTF];
__device__ float  g_Wt[INF * OUTF];
__device__ double g_part[1024];
__device__ float  g_mean;
__device__ float  g_colpart[64 * Nn];
__device__ float  g_rs[Nn];              // 1024 * 2.5 / S[j]
__device__ int    g_mstride;
__device__ unsigned short g_Bf[OUTF * Nn];   // [f][k] fp16 of g[k][f]*1024

// ---------------- mask dtype detection ----------------
__global__ void k_detect(const unsigned char* mask) {
    __shared__ int s[256];
    int nz = 0;
    for (int i = threadIdx.x; i < 65536; i += 256)
        if ((i & 3) != 0 && mask[i]) nz++;
    s[threadIdx.x] = nz;
    __syncthreads();
    for (int o = 128; o > 0; o >>= 1) {
        if (threadIdx.x < o) s[threadIdx.x] += s[threadIdx.x + o];
        __syncthreads();
    }
    if (threadIdx.x == 0) g_mstride = (s[0] == 0) ? 4 : 1;
}

// ---------------- W transpose ----------------
__global__ void k_wt(const float* __restrict__ W) {
    int o = blockIdx.x * 256 + threadIdx.x;
    int f = o & (OUTF - 1);
    int k = o >> 7;
    g_Wt[o] = W[f * INF + k];
}

// ---------------- mean ----------------
__global__ void k_meanpart(const float4* __restrict__ att4) {
    float acc = 0.f;
    int stride = gridDim.x * blockDim.x;
    int n4 = (CN * Nn) / 4;
#pragma unroll 4
    for (int i = blockIdx.x * blockDim.x + threadIdx.x; i < n4; i += stride) {
        float4 v = att4[i];
        acc += (v.x + v.y) + (v.z + v.w);
    }
    __shared__ double s[256];
    s[threadIdx.x] = (double)acc;
    __syncthreads();
    for (int o = 128; o > 0; o >>= 1) {
        if (threadIdx.x < o) s[threadIdx.x] += s[threadIdx.x + o];
        __syncthreads();
    }
    if (threadIdx.x == 0) g_part[blockIdx.x] = s[0];
}

__global__ void k_meanfin() {
    __shared__ double s[256];
    int t = threadIdx.x;
    double a = g_part[t] + g_part[t + 256] + g_part[t + 512] + g_part[t + 768];
    s[t] = a;
    __syncthreads();
    for (int o = 128; o > 0; o >>= 1) {
        if (t < o) s[t] += s[t + o];
        __syncthreads();
    }
    if (t == 0) g_mean = (float)(s[0] / TOTD);
}

// ---------------- column sums (float4 per thread) ----------------
__global__ void k_colsum(const float4* __restrict__ att4) {
    float mean = g_mean;
    int col4 = blockIdx.x * 256 + threadIdx.x;    // 0..1023
    int r0 = blockIdx.y * 256;
    const float4* p = att4 + (size_t)r0 * 1024 + col4;
    float ax = 0.f, ay = 0.f, az = 0.f, aw = 0.f;
#pragma unroll 8
    for (int i = 0; i < 256; i++) {
        float4 v = p[(size_t)i * 1024];
        ax += (v.x > mean) ? __expf(v.x) : 0.f;
        ay += (v.y > mean) ? __expf(v.y) : 0.f;
        az += (v.z > mean) ? __expf(v.z) : 0.f;
        aw += (v.w > mean) ? __expf(v.w) : 0.f;
    }
    float* cp = g_colpart + (size_t)blockIdx.y * Nn + col4 * 4;
    *(float4*)cp = make_float4(ax, ay, az, aw);
}

__global__ void k_rs() {
    int j = blockIdx.x * 256 + threadIdx.x;
    float s = 0.f;
#pragma unroll 8
    for (int ch = 0; ch < 64; ch++) s += g_colpart[ch * Nn + j];
    g_rs[j] = 1024.f * SCALE / s;
}

// ---------------- GEMM1: h = x @ Wt ----------------
__global__ __launch_bounds__(256) void k_gemm1(const float* __restrict__ x) {
    __shared__ __align__(16) float As[16][32];
    __shared__ __align__(16) float Bs[16][128];
    int tid = threadIdx.x;
    int r0 = blockIdx.x * 32;
    int tr = tid >> 4;
    int tc = tid & 15;
    float acc[2][8];
#pragma unroll
    for (int i = 0; i < 2; i++)
#pragma unroll
        for (int j = 0; j < 8; j++) acc[i][j] = 0.f;

    for (int k0 = 0; k0 < INF; k0 += 16) {
        if (tid < 128) {
            int row = tid >> 2, c4 = tid & 3;
            float4 v = *(const float4*)(x + (size_t)(r0 + row) * INF + k0 + c4 * 4);
            As[c4 * 4 + 0][row] = v.x;
            As[c4 * 4 + 1][row] = v.y;
            As[c4 * 4 + 2][row] = v.z;
            As[c4 * 4 + 3][row] = v.w;
        }
#pragma unroll
        for (int q = 0; q < 2; q++) {
            int g = tid + q * 256;
            int kk = g >> 5, f4 = g & 31;
            *(float4*)&Bs[kk][f4 * 4] = *(const float4*)(g_Wt + (k0 + kk) * OUTF + f4 * 4);
        }
        __syncthreads();
#pragma unroll
        for (int kk = 0; kk < 16; kk++) {
            float a0 = As[kk][tr * 2], a1 = As[kk][tr * 2 + 1];
            float b[8];
            *(float4*)(b)     = *(const float4*)&Bs[kk][tc * 8];
            *(float4*)(b + 4) = *(const float4*)&Bs[kk][tc * 8 + 4];
#pragma unroll
            for (int j = 0; j < 8; j++) {
                acc[0][j] += a0 * b[j];
                acc[1][j] += a1 * b[j];
            }
        }
        __syncthreads();
    }
#pragma unroll
    for (int i = 0; i < 2; i++) {
        float* op = g_h + (size_t)(r0 + tr * 2 + i) * OUTF + tc * 8;
        *(float4*)op       = make_float4(acc[i][0], acc[i][1], acc[i][2], acc[i][3]);
        *(float4*)(op + 4) = make_float4(acc[i][4], acc[i][5], acc[i][6], acc[i][7]);
    }
}

// ---------------- B prep ----------------
__global__ void k_bprep() {
    __shared__ float tile[32][33];
    __shared__ float rss[32];
    int k0 = blockIdx.x * 32, f0 = blockIdx.y * 32;
    int t = threadIdx.x;
    {
        int ki = t >> 3, f4 = (t & 7) * 4;
        float4 v = *(const float4*)(g_h + (size_t)(k0 + ki) * OUTF + f0 + f4);
        tile[ki][f4 + 0] = v.x; tile[ki][f4 + 1] = v.y;
        tile[ki][f4 + 2] = v.z; tile[ki][f4 + 3] = v.w;
    }
    if (t < 32) rss[t] = g_rs[k0 + t];
    __syncthreads();
    int fi = t >> 3, k4 = (t & 7) * 4;
    uint32_t p01 = packh2(tile[k4 + 0][fi] * rss[k4 + 0], tile[k4 + 1][fi] * rss[k4 + 1]);
    uint32_t p23 = packh2(tile[k4 + 2][fi] * rss[k4 + 2], tile[k4 + 3][fi] * rss[k4 + 3]);
    size_t o = (size_t)(f0 + fi) * Nn + k0 + k4;
    *(uint2*)(g_Bf + o) = make_uint2(p01, p23);
}

// ---------------- GEMM2 via mma.sync fp16 (R7 structure, BM=64, 2 CTAs/SM) ----------
// A[r,j] = (mask && att>mean) ? exp(att) : 0 -> fp16 on the fly.
// out = (1/1024) * A @ Bf'; block tile 64x128, warp tile 16x64, K-chunk 64,
// double buffered. Stage = 24KB: Af@0 (8KB), Bf@8192 (16KB); stage1 @24K.
__global__ __launch_bounds__(256, 2) void k_gemm2m(const float* __restrict__ att,
                                                   const unsigned char* __restrict__ mask,
                                                   float* __restrict__ out) {
    extern __shared__ __align__(128) char sm[];
    uint32_t smb = smem_to_u32(sm);
    const int tid = threadIdx.x, lane = tid & 31, w = tid >> 5;
    const int r0 = blockIdx.x * 64;
    const float mean = g_mean;
    const int mstride = g_mstride;
    const int wm0 = (w & 3) * 16;
    const int wn0 = (w >> 2) * 64;

    float acc[8][4];
#pragma unroll
    for (int nt = 0; nt < 8; nt++)
#pragma unroll
        for (int q = 0; q < 4; q++) acc[nt][q] = 0.f;

    const int li = lane >> 3;
    const uint32_t aRow = wm0 + (li & 1) * 8 + (lane & 7);
    const uint32_t aKof = (li >> 1) * 16;
    const uint32_t bRow = wn0 + ((lane >> 4) & 1) * 8 + (lane & 7);
    const uint32_t bKof = ((lane >> 3) & 1) * 16;

    float4 va[4];
    uint32_t vmb[4];

#define LOADG(c_)                                                                     \
    {                                                                                 \
        _Pragma("unroll")                                                             \
        for (int i = 0; i < 4; i++) {                                                 \
            int idx = i * 256 + tid;                                                  \
            int m = idx >> 4, c4 = idx & 15;                                          \
            size_t g = (size_t)(r0 + m) * Nn + (c_) * KC + c4 * 4;                    \
            va[i] = *(const float4*)(att + g);                                        \
            if (mstride == 1) {                                                       \
                vmb[i] = *(const uint32_t*)(mask + g);                                \
            } else {                                                                  \
                int4 mi = *(const int4*)((const int*)mask + g);                       \
                vmb[i] = (mi.x ? 1u : 0u) | (mi.y ? 0x100u : 0u) |                    \
                         (mi.z ? 0x10000u : 0u) | (mi.w ? 0x1000000u : 0u);           \
            }                                                                         \
        }                                                                             \
    }

#define STORES(so_)                                                                   \
    {                                                                                 \
        _Pragma("unroll")                                                             \
        for (int i = 0; i < 4; i++) {                                                 \
            int idx = i * 256 + tid;                                                  \
            int m = idx >> 4, c4 = idx & 15;                                          \
            float4 v = va[i]; uint32_t mk = vmb[i];                                   \
            float a0 = ((mk & 0xFFu) && v.x > mean) ? __expf(v.x) : 0.f;              \
            float a1 = ((mk & 0xFF00u) && v.y > mean) ? __expf(v.y) : 0.f;            \
            float a2 = ((mk & 0xFF0000u) && v.z > mean) ? __expf(v.z) : 0.f;          \
            float a3 = ((mk & 0xFF000000u) && v.w > mean) ? __expf(v.w) : 0.f;        \
            uint32_t p01 = packh2(a0, a1);                                            \
            uint32_t p23 = packh2(a2, a3);                                            \
            uint32_t sw = swz((uint32_t)(m * 128 + c4 * 8));                          \
            *(uint2*)(sm + (so_) + sw) = make_uint2(p01, p23);                        \
        }                                                                             \
    }

#define CPB(c_, so_)                                                                  \
    {                                                                                 \
        _Pragma("unroll")                                                             \
        for (int i = 0; i < 4; i++) {                                                 \
            int g = i * 256 + tid;                                                    \
            int f = g >> 3, seg = g & 7;                                              \
            uint32_t sw = swz((uint32_t)(f * 128 + seg * 16));                        \
            const void* sh = (const void*)(g_Bf + (size_t)f * Nn + (c_) * KC + seg * 8); \
            CPASYNC16(smb + (so_) + 8192u + sw, sh);                                  \
        }                                                                             \
    }

    // prologue
    CPB(0, 0u);
    CPCOMMIT();
    LOADG(0);
    STORES(0u);
    CPWAIT0();
    __syncthreads();

    uint32_t so = 0;
    for (int c = 0; c < NCHUNK; c++) {
        uint32_t sn = so ^ 24576u;
        if (c < NCHUNK - 1) {
            CPB(c + 1, sn);
            CPCOMMIT();
            LOADG(c + 1);
        }
#pragma unroll
        for (int ks = 0; ks < 4; ks++) {
            uint32_t ah[4];
            {
                uint32_t sw = swz(aRow * 128 + ks * 32 + aKof);
                LDSM4(ah, smb + so + sw);
            }
#pragma unroll
            for (int nt2 = 0; nt2 < 4; nt2++) {
                uint32_t sw = swz((bRow + nt2 * 16) * 128 + ks * 32 + bKof);
                uint32_t bh[4];
                LDSM4(bh, smb + so + 8192u + sw);
                MMAH(acc[nt2 * 2],     ah, bh[0], bh[1]);
                MMAH(acc[nt2 * 2 + 1], ah, bh[2], bh[3]);
            }
        }
        if (c < NCHUNK - 1) {
            STORES(sn);
            CPWAIT0();
        }
        __syncthreads();
        so = sn;
    }

    // epilogue: unscale + permuted store
    const float dsc = 1.f / 1024.f;
    const int orow = lane >> 2, ocol = (lane & 3) * 2;
#pragma unroll
    for (int nt = 0; nt < 8; nt++) {
        int f = wn0 + nt * 8 + ocol;
        int r1 = r0 + wm0 + orow;
        int n1 = r1 & (Nn - 1), c1 = r1 >> 12;
        *(float2*)(out + (size_t)n1 * 512 + c1 * OUTF + f) =
            make_float2(acc[nt][0] * dsc, acc[nt][1] * dsc);
        int r2 = r1 + 8;
        int n2 = r2 & (Nn - 1), c2 = r2 >> 12;
        *(float2*)(out + (size_t)n2 * 512 + c2 * OUTF + f) =
            make_float2(acc[nt][2] * dsc, acc[nt][3] * dsc);
    }
#undef LOADG
#undef STORES
#undef CPB
}

// ---------------- launch ----------------
extern "C" void kernel_launch(void* const* d_in, const int* in_sizes, int n_in,
                              void* d_out, int out_size) {
    const float* x = (const float*)d_in[0];
    const float* att = (const float*)d_in[1];
    const float* W = (const float*)d_in[2];
    const unsigned char* mask = (const unsigned char*)d_in[3];
    float* out = (float*)d_out;

    static const int SMEM2 = 49152;   // 2 stages x 24KB
    cudaFuncSetAttribute(k_gemm2m, cudaFuncAttributeMaxDynamicSharedMemorySize, SMEM2);

    k_detect<<<1, 256>>>(mask);
    k_wt<<<256, 256>>>(W);
    k_gemm1<<<128, 256>>>(x);
    k_meanpart<<<1024, 256>>>((const float4*)att);
    k_meanfin<<<1, 256>>>();
    k_colsum<<<dim3(4, 64), 256>>>((const float4*)att);
    k_rs<<<16, 256>>>();
    k_bprep<<<dim3(128, 4), 256>>>();
    k_gemm2m<<<256, 256, SMEM2>>>(att, mask, out);
}

// round 11
// speedup vs baseline: 1.3217x; 1.0218x over previous
#include <cuda_runtime.h>
#include <cuda_fp16.h>
#include <stdint.h>
#include <math.h>

#define Nn    4096
#define INF   512
#define OUTF  128
#define CN    16384
#define TOTD  67108864.0
#define SCALE 2.5f
#define KC    64
#define NCHUNK 64

__device__ __forceinline__ uint32_t smem_to_u32(const void* p) {
    uint32_t a;
    asm("{ .reg .u64 t; cvta.to.shared.u64 t, %1; cvt.u32.u64 %0, t; }" : "=r"(a) : "l"(p));
    return a;
}
__device__ __forceinline__ uint32_t packh2(float lo, float hi) {
    uint32_t r;
    asm("cvt.rn.f16x2.f32 %0, %1, %2;" : "=r"(r) : "f"(hi), "f"(lo));
    return r;
}
#define LDSM4(r, a)                                                                   \
    asm volatile("ldmatrix.sync.aligned.m8n8.x4.shared.b16 {%0,%1,%2,%3}, [%4];"      \
        : "=r"((r)[0]), "=r"((r)[1]), "=r"((r)[2]), "=r"((r)[3]) : "r"(a))
#define MMAH(d, a, b0, b1)                                                            \
    asm volatile("mma.sync.aligned.m16n8k16.row.col.f32.f16.f16.f32 "                 \
        "{%0,%1,%2,%3},{%4,%5,%6,%7},{%8,%9},{%0,%1,%2,%3};"                          \
        : "+f"((d)[0]), "+f"((d)[1]), "+f"((d)[2]), "+f"((d)[3])                      \
        : "r"((a)[0]), "r"((a)[1]), "r"((a)[2]), "r"((a)[3]), "r"(b0), "r"(b1))
#define CPASYNC16(dst, src)                                                           \
    asm volatile("cp.async.cg.shared.global [%0], [%1], 16;" :: "r"(dst), "l"(src))
#define CPCOMMIT() asm volatile("cp.async.commit_group;" ::: "memory")
#define CPWAIT0()  asm volatile("cp.async.wait_group 0;" ::: "memory")
// named producer/consumer barriers (count = 512, all threads)
#define BAR_SYNC(id)   asm volatile("bar.sync %0, 512;"   :: "r"(id) : "memory")
#define BAR_ARRIVE(id) asm volatile("bar.arrive %0, 512;" :: "r"(id) : "memory")

__device__ __forceinline__ uint32_t swz(uint32_t off) { return off ^ ((off >> 3) & 0x70); }

// ---------------- scratch ----------------
__device__ float  g_h[Nn * OUTF];
__device__ float  g_Wt[INF * OUTF];
__device__ double g_part[1024];
__device__ float  g_mean;
__device__ float  g_colpart[64 * Nn];
__device__ float  g_rs[Nn];              // 1024 * 2.5 / S[j]
__device__ int    g_mstride;
__device__ unsigned short g_Bf[OUTF * Nn];   // [f][k] fp16 of g[k][f]*1024

// ---------------- mask dtype detection ----------------
__global__ void k_detect(const unsigned char* mask) {
    __shared__ int s[256];
    int nz = 0;
    for (int i = threadIdx.x; i < 65536; i += 256)
        if ((i & 3) != 0 && mask[i]) nz++;
    s[threadIdx.x] = nz;
    __syncthreads();
    for (int o = 128; o > 0; o >>= 1) {
        if (threadIdx.x < o) s[threadIdx.x] += s[threadIdx.x + o];
        __syncthreads();
    }
    if (threadIdx.x == 0) g_mstride = (s[0] == 0) ? 4 : 1;
}

// ---------------- W transpose ----------------
__global__ void k_wt(const float* __restrict__ W) {
    int o = blockIdx.x * 256 + threadIdx.x;
    int f = o & (OUTF - 1);
    int k = o >> 7;
    g_Wt[o] = W[f * INF + k];
}

// ---------------- mean ----------------
__global__ void k_meanpart(const float4* __restrict__ att4) {
    float acc = 0.f;
    int stride = gridDim.x * blockDim.x;
    int n4 = (CN * Nn) / 4;
#pragma unroll 4
    for (int i = blockIdx.x * blockDim.x + threadIdx.x; i < n4; i += stride) {
        float4 v = att4[i];
        acc += (v.x + v.y) + (v.z + v.w);
    }
    __shared__ double s[256];
    s[threadIdx.x] = (double)acc;
    __syncthreads();
    for (int o = 128; o > 0; o >>= 1) {
        if (threadIdx.x < o) s[threadIdx.x] += s[threadIdx.x + o];
        __syncthreads();
    }
    if (threadIdx.x == 0) g_part[blockIdx.x] = s[0];
}

__global__ void k_meanfin() {
    __shared__ double s[256];
    int t = threadIdx.x;
    double a = g_part[t] + g_part[t + 256] + g_part[t + 512] + g_part[t + 768];
    s[t] = a;
    __syncthreads();
    for (int o = 128; o > 0; o >>= 1) {
        if (t < o) s[t] += s[t + o];
        __syncthreads();
    }
    if (t == 0) g_mean = (float)(s[0] / TOTD);
}

// ---------------- column sums (float4 per thread) ----------------
__global__ void k_colsum(const float4* __restrict__ att4) {
    float mean = g_mean;
    int col4 = blockIdx.x * 256 + threadIdx.x;    // 0..1023
    int r0 = blockIdx.y * 256;
    const float4* p = att4 + (size_t)r0 * 1024 + col4;
    float ax = 0.f, ay = 0.f, az = 0.f, aw = 0.f;
#pragma unroll 8
    for (int i = 0; i < 256; i++) {
        float4 v = p[(size_t)i * 1024];
        ax += (v.x > mean) ? __expf(v.x) : 0.f;
        ay += (v.y > mean) ? __expf(v.y) : 0.f;
        az += (v.z > mean) ? __expf(v.z) : 0.f;
        aw += (v.w > mean) ? __expf(v.w) : 0.f;
    }
    float* cp = g_colpart + (size_t)blockIdx.y * Nn + col4 * 4;
    *(float4*)cp = make_float4(ax, ay, az, aw);
}

__global__ void k_rs() {
    int j = blockIdx.x * 256 + threadIdx.x;
    float s = 0.f;
#pragma unroll 8
    for (int ch = 0; ch < 64; ch++) s += g_colpart[ch * Nn + j];
    g_rs[j] = 1024.f * SCALE / s;
}

// ---------------- GEMM1: h = x @ Wt ----------------
__global__ __launch_bounds__(256) void k_gemm1(const float* __restrict__ x) {
    __shared__ __align__(16) float As[16][32];
    __shared__ __align__(16) float Bs[16][128];
    int tid = threadIdx.x;
    int r0 = blockIdx.x * 32;
    int tr = tid >> 4;
    int tc = tid & 15;
    float acc[2][8];
#pragma unroll
    for (int i = 0; i < 2; i++)
#pragma unroll
        for (int j = 0; j < 8; j++) acc[i][j] = 0.f;

    for (int k0 = 0; k0 < INF; k0 += 16) {
        if (tid < 128) {
            int row = tid >> 2, c4 = tid & 3;
            float4 v = *(const float4*)(x + (size_t)(r0 + row) * INF + k0 + c4 * 4);
            As[c4 * 4 + 0][row] = v.x;
            As[c4 * 4 + 1][row] = v.y;
            As[c4 * 4 + 2][row] = v.z;
            As[c4 * 4 + 3][row] = v.w;
        }
#pragma unroll
        for (int q = 0; q < 2; q++) {
            int g = tid + q * 256;
            int kk = g >> 5, f4 = g & 31;
            *(float4*)&Bs[kk][f4 * 4] = *(const float4*)(g_Wt + (k0 + kk) * OUTF + f4 * 4);
        }
        __syncthreads();
#pragma unroll
        for (int kk = 0; kk < 16; kk++) {
            float a0 = As[kk][tr * 2], a1 = As[kk][tr * 2 + 1];
            float b[8];
            *(float4*)(b)     = *(const float4*)&Bs[kk][tc * 8];
            *(float4*)(b + 4) = *(const float4*)&Bs[kk][tc * 8 + 4];
#pragma unroll
            for (int j = 0; j < 8; j++) {
                acc[0][j] += a0 * b[j];
                acc[1][j] += a1 * b[j];
            }
        }
        __syncthreads();
    }
#pragma unroll
    for (int i = 0; i < 2; i++) {
        float* op = g_h + (size_t)(r0 + tr * 2 + i) * OUTF + tc * 8;
        *(float4*)op       = make_float4(acc[i][0], acc[i][1], acc[i][2], acc[i][3]);
        *(float4*)(op + 4) = make_float4(acc[i][4], acc[i][5], acc[i][6], acc[i][7]);
    }
}

// ---------------- B prep ----------------
__global__ void k_bprep() {
    __shared__ float tile[32][33];
    __shared__ float rss[32];
    int k0 = blockIdx.x * 32, f0 = blockIdx.y * 32;
    int t = threadIdx.x;
    {
        int ki = t >> 3, f4 = (t & 7) * 4;
        float4 v = *(const float4*)(g_h + (size_t)(k0 + ki) * OUTF + f0 + f4);
        tile[ki][f4 + 0] = v.x; tile[ki][f4 + 1] = v.y;
        tile[ki][f4 + 2] = v.z; tile[ki][f4 + 3] = v.w;
    }
    if (t < 32) rss[t] = g_rs[k0 + t];
    __syncthreads();
    int fi = t >> 3, k4 = (t & 7) * 4;
    uint32_t p01 = packh2(tile[k4 + 0][fi] * rss[k4 + 0], tile[k4 + 1][fi] * rss[k4 + 1]);
    uint32_t p23 = packh2(tile[k4 + 2][fi] * rss[k4 + 2], tile[k4 + 3][fi] * rss[k4 + 3]);
    size_t o = (size_t)(f0 + fi) * Nn + k0 + k4;
    *(uint2*)(g_Bf + o) = make_uint2(p01, p23);
}

// ---------------- GEMM2: warp-specialized fp16 mma.sync ----------------
// 512 threads: warps 0-7 consumers (MMA, tile 128x128, warp tile 32x64),
// warps 8-15 producers (LDG att/mask -> exp -> fp16 STS; cp.async B).
// 2 stages: A-f16 @ 0/16K, B-f16 @ 32K/48K. Named barriers:
//   FULL[s]  = 1+s : producers arrive, consumers sync
//   EMPTY[s] = 3+s : consumers arrive, producers sync (skip first 2 chunks)
__global__ __launch_bounds__(512, 1) void k_gemm2m(const float* __restrict__ att,
                                                   const unsigned char* __restrict__ mask,
                                                   float* __restrict__ out) {
    extern __shared__ __align__(128) char sm[];
    uint32_t smb = smem_to_u32(sm);
    const int tid = threadIdx.x, lane = tid & 31, w = tid >> 5;
    const int r0 = blockIdx.x * 128;

    if (w < 8) {
        // ---------------- consumers ----------------
        const int wm0 = (w & 3) * 32;
        const int wn0 = (w >> 2) * 64;
        float acc[2][8][4];
#pragma unroll
        for (int mt = 0; mt < 2; mt++)
#pragma unroll
            for (int nt = 0; nt < 8; nt++)
#pragma unroll
                for (int q = 0; q < 4; q++) acc[mt][nt][q] = 0.f;

        const int li = lane >> 3;
        const uint32_t aRow = wm0 + (li & 1) * 8 + (lane & 7);
        const uint32_t aKof = (li >> 1) * 16;
        const uint32_t bRow = wn0 + ((lane >> 4) & 1) * 8 + (lane & 7);
        const uint32_t bKof = ((lane >> 3) & 1) * 16;

        for (int c = 0; c < NCHUNK; c++) {
            int s = c & 1;
            BAR_SYNC(1 + s);
            uint32_t abase = smb + (uint32_t)s * 16384u;
            uint32_t bbase = smb + 32768u + (uint32_t)s * 16384u;
#pragma unroll
            for (int ks = 0; ks < 4; ks++) {
                uint32_t ah[2][4];
#pragma unroll
                for (int mt = 0; mt < 2; mt++) {
                    uint32_t sw = swz((aRow + mt * 16) * 128 + ks * 32 + aKof);
                    LDSM4(ah[mt], abase + sw);
                }
#pragma unroll
                for (int nt2 = 0; nt2 < 4; nt2++) {
                    uint32_t sw = swz((bRow + nt2 * 16) * 128 + ks * 32 + bKof);
                    uint32_t bh[4];
                    LDSM4(bh, bbase + sw);
#pragma unroll
                    for (int mt = 0; mt < 2; mt++) {
                        MMAH(acc[mt][nt2 * 2],     ah[mt], bh[0], bh[1]);
                        MMAH(acc[mt][nt2 * 2 + 1], ah[mt], bh[2], bh[3]);
                    }
                }
            }
            BAR_ARRIVE(3 + s);
        }

        // epilogue: unscale + permuted store
        const float dsc = 1.f / 1024.f;
        const int orow = lane >> 2, ocol = (lane & 3) * 2;
#pragma unroll
        for (int mt = 0; mt < 2; mt++) {
#pragma unroll
            for (int nt = 0; nt < 8; nt++) {
                int f = wn0 + nt * 8 + ocol;
                int r1 = r0 + wm0 + mt * 16 + orow;
                int n1 = r1 & (Nn - 1), c1 = r1 >> 12;
                *(float2*)(out + (size_t)n1 * 512 + c1 * OUTF + f) =
                    make_float2(acc[mt][nt][0] * dsc, acc[mt][nt][1] * dsc);
                int r2 = r1 + 8;
                int n2 = r2 & (Nn - 1), c2 = r2 >> 12;
                *(float2*)(out + (size_t)n2 * 512 + c2 * OUTF + f) =
                    make_float2(acc[mt][nt][2] * dsc, acc[mt][nt][3] * dsc);
            }
        }
    } else {
        // ---------------- producers ----------------
        const int tid2 = tid - 256;                  // 0..255
        const float mean = g_mean;
        const int mstride = g_mstride;
        float4 va[8];
        uint32_t vmb[8];

#define LOADG(c_)                                                                     \
        {                                                                             \
            _Pragma("unroll")                                                         \
            for (int i = 0; i < 8; i++) {                                             \
                int idx = i * 256 + tid2;                                             \
                int m = idx >> 4, c4 = idx & 15;                                      \
                size_t g = (size_t)(r0 + m) * Nn + (c_) * KC + c4 * 4;                \
                va[i] = *(const float4*)(att + g);                                    \
                if (mstride == 1) {                                                   \
                    vmb[i] = *(const uint32_t*)(mask + g);                            \
                } else {                                                              \
                    int4 mi = *(const int4*)((const int*)mask + g);                   \
                    vmb[i] = (mi.x ? 1u : 0u) | (mi.y ? 0x100u : 0u) |                \
                             (mi.z ? 0x10000u : 0u) | (mi.w ? 0x1000000u : 0u);       \
                }                                                                     \
            }                                                                         \
        }

        LOADG(0);
        for (int c = 0; c < NCHUNK; c++) {
            int s = c & 1;
            if (c >= 2) BAR_SYNC(3 + s);
            // B tile cp.async into freed stage
#pragma unroll
            for (int i = 0; i < 4; i++) {
                int g = i * 256 + tid2;
                int f = g >> 3, seg = g & 7;
                uint32_t sw = swz((uint32_t)(f * 128 + seg * 16));
                CPASYNC16(smb + 32768u + (uint32_t)s * 16384u + sw,
                          g_Bf + (size_t)f * Nn + c * KC + seg * 8);
            }
            CPCOMMIT();
            // convert A (registers from LOADG(c)) into stage s
            uint32_t so = (uint32_t)s * 16384u;
#pragma unroll
            for (int i = 0; i < 8; i++) {
                int idx = i * 256 + tid2;
                int m = idx >> 4, c4 = idx & 15;
                float4 v = va[i]; uint32_t mk = vmb[i];
                float a0 = ((mk & 0xFFu) && v.x > mean) ? __expf(v.x) : 0.f;
                float a1 = ((mk & 0xFF00u) && v.y > mean) ? __expf(v.y) : 0.f;
                float a2 = ((mk & 0xFF0000u) && v.z > mean) ? __expf(v.z) : 0.f;
                float a3 = ((mk & 0xFF000000u) && v.w > mean) ? __expf(v.w) : 0.f;
                uint32_t p01 = packh2(a0, a1);
                uint32_t p23 = packh2(a2, a3);
                uint32_t sw = swz((uint32_t)(m * 128 + c4 * 8));
                *(uint2*)(sm + so + sw) = make_uint2(p01, p23);
            }
            if (c < NCHUNK - 1) LOADG(c + 1);
            CPWAIT0();
            BAR_ARRIVE(1 + s);
        }
#undef LOADG
    }
}

// ---------------- launch ----------------
extern "C" void kernel_launch(void* const* d_in, const int* in_sizes, int n_in,
                              void* d_out, int out_size) {
    const float* x = (const float*)d_in[0];
    const float* att = (const float*)d_in[1];
    const float* W = (const float*)d_in[2];
    const unsigned char* mask = (const unsigned char*)d_in[3];
    float* out = (float*)d_out;

    static const int SMEM2 = 65536;   // A: 2x16KB, B: 2x16KB
    cudaFuncSetAttribute(k_gemm2m, cudaFuncAttributeMaxDynamicSharedMemorySize, SMEM2);

    k_detect<<<1, 256>>>(mask);
    k_wt<<<256, 256>>>(W);
    k_gemm1<<<128, 256>>>(x);
    k_meanpart<<<1024, 256>>>((const float4*)att);
    k_meanfin<<<1, 256>>>();
    k_colsum<<<dim3(4, 64), 256>>>((const float4*)att);
    k_rs<<<16, 256>>>();
    k_bprep<<<dim3(128, 4), 256>>>();
    k_gemm2m<<<128, 512, SMEM2>>>(att, mask, out);
}